// round 1
// baseline (speedup 1.0000x reference)
#include <cuda_runtime.h>
#include <cuda_bf16.h>
#include <math.h>

// Problem constants
#define N_NODES   512
#define IN_FEAT   512
#define N_HEADS   8
#define N_HID     64
#define NEG_SLOPE 0.2f

// Scratch (device globals: allocation-free rule)
__device__ float d_gsrc[N_HEADS * N_NODES * N_HID];   // [h][n][f]  1 MB
__device__ float d_gtgt[N_HEADS * N_NODES * N_HID];   // [h][n][f]  1 MB
__device__ float d_attn[N_HEADS * N_NODES * N_NODES]; // [h][i][j]  8 MB

// ---------------------------------------------------------------------------
// K1: fused GEMM  g = x @ W^T for both W_source and W_target.
// Block computes a 64(n) x 64(r) tile; r-tile maps to exactly one head of one
// weight matrix, so writes go straight into g[h][n][f] layout.
// ---------------------------------------------------------------------------
__global__ void k1_gemm(const float* __restrict__ x,
                        const float* __restrict__ Ws,
                        const float* __restrict__ Wt) {
    __shared__ float As[64][17];
    __shared__ float Bs[64][17];

    const int n0 = blockIdx.x * 64;
    const int r0 = blockIdx.y * 64;           // 0..1023
    const float* W   = (r0 < 512) ? Ws : Wt;
    float*       gout= (r0 < 512) ? d_gsrc : d_gtgt;
    const int rb = r0 & 511;
    const int h  = rb >> 6;

    const int t  = threadIdx.x;
    const int tx = t & 15, ty = t >> 4;

    float c[4][4] = {};

    for (int k0 = 0; k0 < IN_FEAT; k0 += 16) {
        const int d = t & 15, nr = t >> 4;
        #pragma unroll
        for (int it = 0; it < 4; it++) {
            const int n = nr + it * 16;
            As[n][d] = x[(n0 + n) * IN_FEAT + k0 + d];
            Bs[n][d] = W[(rb + n) * IN_FEAT + k0 + d];
        }
        __syncthreads();
        #pragma unroll
        for (int d2 = 0; d2 < 16; d2++) {
            float a[4], b[4];
            #pragma unroll
            for (int i = 0; i < 4; i++) a[i] = As[ty + 16 * i][d2];
            #pragma unroll
            for (int j = 0; j < 4; j++) b[j] = Bs[tx + 16 * j][d2];
            #pragma unroll
            for (int i = 0; i < 4; i++)
                #pragma unroll
                for (int j = 0; j < 4; j++)
                    c[i][j] = fmaf(a[i], b[j], c[i][j]);
        }
        __syncthreads();
    }

    #pragma unroll
    for (int i = 0; i < 4; i++) {
        const int n = n0 + ty + 16 * i;
        float* dst = gout + h * (N_NODES * N_HID) + n * N_HID;
        #pragma unroll
        for (int j = 0; j < 4; j++)
            dst[tx + 16 * j] = c[i][j];
    }
}

// ---------------------------------------------------------------------------
// K2: scores + adjacency mask + softmax over j, written to d_attn[h][i][j].
// Block = (32-row i-tile, head). gs tiles streamed through smem (16 chunks of
// 32 j). LeakyReLU folded as: acc += t * (t>=0 ? w : 0.2w).
// ---------------------------------------------------------------------------
#define K2_SMEM_FLOATS (32 * 512 + 2 * 32 * 65 + 128)
__global__ void k2_scores(const float* __restrict__ attn_w,
                          const int*   __restrict__ adj) {
    extern __shared__ float sm[];
    float* sc  = sm;                        // 32 x 512 scores
    float* sgt = sm + 32 * 512;             // 32 x 65
    float* sgs = sgt + 32 * 65;             // 32 x 65
    float* wp  = sgs + 32 * 65;             // 64
    float* wn  = wp + 64;                   // 64

    const int h  = blockIdx.y;
    const int i0 = blockIdx.x * 32;
    const int t  = threadIdx.x;

    const float* gt_h = d_gtgt + h * (N_NODES * N_HID);
    const float* gs_h = d_gsrc + h * (N_NODES * N_HID);

    if (t < 64) { const float w = attn_w[t]; wp[t] = w; wn[t] = NEG_SLOPE * w; }

    #pragma unroll
    for (int k = 0; k < 8; k++) {
        const int lin = t + k * 256;
        const int i = lin >> 6, f = lin & 63;
        sgt[i * 65 + f] = gt_h[(i0 + i) * N_HID + f];
    }
    __syncthreads();

    const int tj = t & 15, ti = t >> 4;
    const float* gt0p = sgt + (2 * ti) * 65;
    const float* gt1p = gt0p + 65;
    const float* gs0p = sgs + (2 * tj) * 65;
    const float* gs1p = gs0p + 65;

    for (int jc = 0; jc < 16; jc++) {
        const int j0 = jc * 32;
        #pragma unroll
        for (int k = 0; k < 8; k++) {
            const int lin = t + k * 256;
            const int j = lin >> 6, f = lin & 63;
            sgs[j * 65 + f] = gs_h[(j0 + j) * N_HID + f];
        }
        __syncthreads();

        float a00 = 0.f, a01 = 0.f, a10 = 0.f, a11 = 0.f;
        #pragma unroll
        for (int f = 0; f < 64; f++) {
            const float wpf = wp[f], wnf = wn[f];
            const float g0 = gt0p[f], g1 = gt1p[f];
            const float s0 = gs0p[f], s1 = gs1p[f];
            const float t00 = g0 + s0, t01 = g0 + s1;
            const float t10 = g1 + s0, t11 = g1 + s1;
            a00 = fmaf(t00, (t00 >= 0.f) ? wpf : wnf, a00);
            a01 = fmaf(t01, (t01 >= 0.f) ? wpf : wnf, a01);
            a10 = fmaf(t10, (t10 >= 0.f) ? wpf : wnf, a10);
            a11 = fmaf(t11, (t11 >= 0.f) ? wpf : wnf, a11);
        }
        sc[(2 * ti)     * 512 + j0 + 2 * tj]     = a00;
        sc[(2 * ti)     * 512 + j0 + 2 * tj + 1] = a01;
        sc[(2 * ti + 1) * 512 + j0 + 2 * tj]     = a10;
        sc[(2 * ti + 1) * 512 + j0 + 2 * tj + 1] = a11;
        __syncthreads();
    }

    // Softmax over j. Warp w owns rows 4w..4w+3.
    const int wrp = t >> 5, lane = t & 31;
    #pragma unroll 1
    for (int r = 0; r < 4; r++) {
        const int i  = wrp * 4 + r;
        const int gi = i0 + i;
        float* row = sc + i * 512;
        const int* arow = adj + gi * N_NODES;

        float mx = -INFINITY;
        #pragma unroll
        for (int k = 0; k < 16; k++) {
            const int j = lane + k * 32;
            float v = row[j];
            v = arow[j] ? v : -INFINITY;
            row[j] = v;
            mx = fmaxf(mx, v);
        }
        #pragma unroll
        for (int o = 16; o; o >>= 1) mx = fmaxf(mx, __shfl_xor_sync(0xffffffffu, mx, o));

        float s = 0.f;
        #pragma unroll
        for (int k = 0; k < 16; k++) {
            const int j = lane + k * 32;
            const float e = __expf(row[j] - mx);
            row[j] = e;
            s += e;
        }
        #pragma unroll
        for (int o = 16; o; o >>= 1) s += __shfl_xor_sync(0xffffffffu, s, o);
        const float inv = 1.f / s;

        float* dst = d_attn + h * (N_NODES * N_NODES) + gi * N_NODES;
        #pragma unroll
        for (int k = 0; k < 16; k++) {
            const int j = lane + k * 32;
            dst[j] = row[j] * inv;
        }
    }
}

// ---------------------------------------------------------------------------
// K3: out[i, h*64+f] = sum_j attn[h][i][j] * g_tgt[h][j][f]
// Block = (32-row i-tile, head); 2i x 4f register micro-tile.
// ---------------------------------------------------------------------------
__global__ void k3_out(float* __restrict__ out) {
    __shared__ float sa[32][33];
    __shared__ float sb[32][64];

    const int i0 = blockIdx.x * 32;
    const int h  = blockIdx.y;
    const int t  = threadIdx.x;
    const int tf = t & 15, ti = t >> 4;

    const float* attn_h = d_attn + h * (N_NODES * N_NODES);
    const float* gt_h   = d_gtgt + h * (N_NODES * N_HID);

    float acc[2][4] = {};

    for (int j0 = 0; j0 < N_NODES; j0 += 32) {
        #pragma unroll
        for (int k = 0; k < 4; k++) {
            const int lin = t + k * 256;
            const int i = lin >> 5, j = lin & 31;
            sa[i][j] = attn_h[(i0 + i) * N_NODES + j0 + j];
        }
        #pragma unroll
        for (int k = 0; k < 8; k++) {
            const int lin = t + k * 256;
            const int j = lin >> 6, f = lin & 63;
            sb[j][f] = gt_h[(j0 + j) * N_HID + f];
        }
        __syncthreads();
        #pragma unroll
        for (int j = 0; j < 32; j++) {
            const float a0 = sa[2 * ti][j];
            const float a1 = sa[2 * ti + 1][j];
            #pragma unroll
            for (int ff = 0; ff < 4; ff++) {
                const float b = sb[j][tf + 16 * ff];
                acc[0][ff] = fmaf(a0, b, acc[0][ff]);
                acc[1][ff] = fmaf(a1, b, acc[1][ff]);
            }
        }
        __syncthreads();
    }

    #pragma unroll
    for (int ii = 0; ii < 2; ii++) {
        const int i = i0 + 2 * ti + ii;
        #pragma unroll
        for (int ff = 0; ff < 4; ff++)
            out[i * (N_HEADS * N_HID) + h * N_HID + tf + 16 * ff] = acc[ii][ff];
    }
}

// ---------------------------------------------------------------------------
// K4: transpose d_attn[h][i][j] -> attention output [i][j][h] (coalesced both
// sides via padded smem tile). One block per i.
// ---------------------------------------------------------------------------
__global__ void k4_transpose(float* __restrict__ att_out) {
    __shared__ float s[8 * 516];
    const int i = blockIdx.x;
    const int t = threadIdx.x;

    #pragma unroll
    for (int k = 0; k < 16; k++) {
        const int lin = t + k * 256;
        const int hh = lin >> 9, j = lin & 511;
        s[hh * 516 + j] = d_attn[hh * (N_NODES * N_NODES) + i * N_NODES + j];
    }
    __syncthreads();

    float* dst = att_out + i * (N_NODES * N_HEADS);
    #pragma unroll
    for (int k = 0; k < 16; k++) {
        const int lin = t + k * 256;
        const int j = lin >> 3, hh = lin & 7;
        dst[lin] = s[hh * 516 + j];
    }
}

// ---------------------------------------------------------------------------
extern "C" void kernel_launch(void* const* d_in, const int* in_sizes, int n_in,
                              void* d_out, int out_size) {
    const float* x   = (const float*)d_in[0];  // h [1,512,512]
    const float* Ws  = (const float*)d_in[1];  // W_source [512,512]
    const float* Wt  = (const float*)d_in[2];  // W_target [512,512]
    const float* aw  = (const float*)d_in[3];  // attn_w [64]
    const int*   adj = (const int*)d_in[4];    // adjacency [512,512,1]

    float* out = (float*)d_out;
    float* att_out = out + N_NODES * N_HEADS * N_HID;  // after out [512,512]

    const int k2_smem = K2_SMEM_FLOATS * (int)sizeof(float);
    cudaFuncSetAttribute(k2_scores, cudaFuncAttributeMaxDynamicSharedMemorySize, k2_smem);

    k1_gemm<<<dim3(8, 16), 256>>>(x, Ws, Wt);
    k2_scores<<<dim3(16, 8), 256, k2_smem>>>(aw, adj);
    k3_out<<<dim3(16, 8), 256>>>(out);
    // Attention output only if the harness buffer includes it.
    if (out_size >= N_NODES * N_HEADS * N_HID + N_NODES * N_NODES * N_HEADS) {
        k4_transpose<<<N_NODES, 256>>>(att_out);
    }
}

// round 2
// speedup vs baseline: 1.5309x; 1.5309x over previous
#include <cuda_runtime.h>
#include <math.h>

#define N_NODES   512
#define IN_FEAT   512
#define N_HEADS   8
#define N_HID     64

typedef unsigned long long u64;

// Scratch (device globals: allocation-free rule)
__device__ float d_gsrc[N_HEADS * N_NODES * N_HID];   // [h][n][f]
__device__ float d_gtgt[N_HEADS * N_NODES * N_HID];   // [h][n][f]
__device__ float d_attn[N_HEADS * N_NODES * N_NODES]; // [h][i][j]
__device__ float d_u[N_HEADS * N_NODES];              // 0.6 * <w, gsrc[j]>
__device__ float d_v[N_HEADS * N_NODES];              // 0.6 * <w, gtgt[i]>

// ---- packed f32x2 helpers (FFMA2 / FADD2 per SASS_QUICKREF pattern) ----
__device__ __forceinline__ u64 pack2(float x, float y) {
    u64 r; asm("mov.b64 %0, {%1,%2};" : "=l"(r) : "f"(x), "f"(y)); return r;
}
__device__ __forceinline__ void unpack2(u64 v, float& x, float& y) {
    asm("mov.b64 {%0,%1}, %2;" : "=f"(x), "=f"(y) : "l"(v));
}
__device__ __forceinline__ u64 add2(u64 a, u64 b) {
    u64 d; asm("add.rn.f32x2 %0, %1, %2;" : "=l"(d) : "l"(a), "l"(b)); return d;
}
__device__ __forceinline__ u64 fma2(u64 a, u64 b, u64 c) {
    u64 d; asm("fma.rn.f32x2 %0, %1, %2, %3;" : "=l"(d) : "l"(a), "l"(b), "l"(c)); return d;
}

// ---------------------------------------------------------------------------
// K1: g = x @ W^T for both weights, FFMA2 (j-pairs packed).
// Epilogue also produces u (from gsrc) / v (from gtgt): 0.6 * <attn_w, row>.
// Block tile: 64 n x 64 r, r-tile = one head of one weight matrix.
// ---------------------------------------------------------------------------
__global__ __launch_bounds__(256) void k1_gemm(const float* __restrict__ x,
                                               const float* __restrict__ Ws,
                                               const float* __restrict__ Wt,
                                               const float* __restrict__ aw) {
    __shared__ float As[64][17];
    __shared__ float Bt[16][66];   // transposed: [d][j]

    const int n0 = blockIdx.x * 64;
    const int r0 = blockIdx.y * 64;           // 0..1023
    const float* W    = (r0 < 512) ? Ws : Wt;
    float*       gout = (r0 < 512) ? d_gsrc : d_gtgt;
    float*       uv   = (r0 < 512) ? d_u : d_v;
    const int rb = r0 & 511;
    const int h  = rb >> 6;

    const int t  = threadIdx.x;
    const int tx = t & 15, ty = t >> 4;

    u64 acc[4][2] = {};   // [ii][jp], j = 2tx + 32*jp (+1)

    for (int k0 = 0; k0 < IN_FEAT; k0 += 16) {
        #pragma unroll
        for (int it = 0; it < 4; it++)
            As[ty + 16 * it][tx] = x[(n0 + ty + 16 * it) * IN_FEAT + k0 + tx];
        #pragma unroll
        for (int kk = 0; kk < 4; kk++) {
            const int lin = t + kk * 256;
            const int d = lin & 15, j = lin >> 4;
            Bt[d][j] = W[(rb + j) * IN_FEAT + k0 + d];
        }
        __syncthreads();
        #pragma unroll
        for (int d2 = 0; d2 < 16; d2++) {
            const u64 b0 = *(const u64*)&Bt[d2][2 * tx];
            const u64 b1 = *(const u64*)&Bt[d2][2 * tx + 32];
            #pragma unroll
            for (int ii = 0; ii < 4; ii++) {
                const float a = As[ty + 16 * ii][d2];
                const u64 a2 = pack2(a, a);
                acc[ii][0] = fma2(a2, b0, acc[ii][0]);
                acc[ii][1] = fma2(a2, b1, acc[ii][1]);
            }
        }
        __syncthreads();
    }

    const float w00 = 0.6f * aw[2 * tx],      w01 = 0.6f * aw[2 * tx + 1];
    const float w10 = 0.6f * aw[2 * tx + 32], w11 = 0.6f * aw[2 * tx + 33];

    #pragma unroll
    for (int ii = 0; ii < 4; ii++) {
        const int n = n0 + ty + 16 * ii;
        float* dst = gout + h * (N_NODES * N_HID) + n * N_HID;
        float c00, c01, c10, c11;
        unpack2(acc[ii][0], c00, c01);
        unpack2(acc[ii][1], c10, c11);
        *(float2*)&dst[2 * tx]      = make_float2(c00, c01);
        *(float2*)&dst[2 * tx + 32] = make_float2(c10, c11);
        float p = w00 * c00 + w01 * c01 + w10 * c10 + w11 * c11;
        #pragma unroll
        for (int off = 8; off; off >>= 1)
            p += __shfl_down_sync(0xffffffffu, p, off, 16);
        if (tx == 0) uv[h * N_NODES + n] = p;
    }
}

// ---------------------------------------------------------------------------
// K2: A[i,j] = sum_f (0.4 w_f)|gs_jf + gt_if|  (packed f32x2, abs via LOP3),
// then score = A + u_j + v_i, adjacency mask, softmax over j -> d_attn[h][i][j].
// Scores live entirely in registers (each lane softmaxes exactly its own j's).
// Block = (32 i-rows, head). gs strip [fp][j] in smem (conflict-free LDS.64).
// ---------------------------------------------------------------------------
#define K2_SMEM_BYTES (32 * 512 * 8 + (32 * 66 + 64 + 512 + 32) * 4)

__global__ __launch_bounds__(256, 1) void k2_scores(const float* __restrict__ aw,
                                                    const int*   __restrict__ adj) {
    extern __shared__ char k2sm[];
    u64*   sgs = (u64*)k2sm;                       // [32 fp][512 j]
    float* sgt = (float*)(k2sm + 32 * 512 * 8);    // [32 i][66]
    float* sw  = sgt + 32 * 66;                    // 64 (0.4*w)
    float* su  = sw + 64;                          // 512
    float* sv  = su + 512;                         // 32

    const int h  = blockIdx.y;
    const int i0 = blockIdx.x * 32;
    const int t  = threadIdx.x;

    const float* gs_h = d_gsrc + h * (N_NODES * N_HID);
    const float* gt_h = d_gtgt + h * (N_NODES * N_HID);

    if (t < 64) sw[t] = 0.4f * aw[t];
    su[t]       = d_u[h * N_NODES + t];
    su[t + 256] = d_u[h * N_NODES + t + 256];
    if (t < 32) sv[t] = d_v[h * N_NODES + i0 + t];

    #pragma unroll
    for (int k = 0; k < 8; k++) {
        const int lin = t + k * 256;
        const int i = lin >> 6, f = lin & 63;
        sgt[i * 66 + f] = gt_h[(i0 + i) * N_HID + f];
    }
    #pragma unroll
    for (int k = 0; k < 32; k++) {
        const int lin = t + k * 256;           // over 8192 float4
        const int j = lin & 511, f4 = lin >> 9;
        const float4 vv = *(const float4*)&gs_h[j * N_HID + 4 * f4];
        sgs[(2 * f4)     * 512 + j] = pack2(vv.x, vv.y);
        sgs[(2 * f4 + 1) * 512 + j] = pack2(vv.z, vv.w);
    }
    __syncthreads();

    const int ti = t >> 5, tj = t & 31;        // warp ti owns rows 4ti..4ti+3
    const u64 ABS2 = 0x7FFFFFFF7FFFFFFFULL;
    float vals[4][16];

    #pragma unroll
    for (int jt = 0; jt < 4; jt++) {
        u64 acc[4][4] = {};
        #pragma unroll 8
        for (int fp = 0; fp < 32; fp++) {
            const u64 w2 = *(const u64*)&sw[2 * fp];
            const u64 g0 = *(const u64*)&sgt[(4 * ti + 0) * 66 + 2 * fp];
            const u64 g1 = *(const u64*)&sgt[(4 * ti + 1) * 66 + 2 * fp];
            const u64 g2 = *(const u64*)&sgt[(4 * ti + 2) * 66 + 2 * fp];
            const u64 g3 = *(const u64*)&sgt[(4 * ti + 3) * 66 + 2 * fp];
            #pragma unroll
            for (int jj = 0; jj < 4; jj++) {
                const u64 s2 = sgs[fp * 512 + tj + 32 * (4 * jt + jj)];
                const u64 t0 = add2(g0, s2) & ABS2;
                const u64 t1 = add2(g1, s2) & ABS2;
                const u64 t2 = add2(g2, s2) & ABS2;
                const u64 t3 = add2(g3, s2) & ABS2;
                acc[0][jj] = fma2(t0, w2, acc[0][jj]);
                acc[1][jj] = fma2(t1, w2, acc[1][jj]);
                acc[2][jj] = fma2(t2, w2, acc[2][jj]);
                acc[3][jj] = fma2(t3, w2, acc[3][jj]);
            }
        }
        #pragma unroll
        for (int ii = 0; ii < 4; ii++)
            #pragma unroll
            for (int jj = 0; jj < 4; jj++) {
                float lo, hi; unpack2(acc[ii][jj], lo, hi);
                vals[ii][4 * jt + jj] = lo + hi;
            }
    }

    // Softmax per row (register-resident; lane tj holds j = tj + 32m)
    #pragma unroll
    for (int ii = 0; ii < 4; ii++) {
        const int i  = 4 * ti + ii;
        const int gi = i0 + i;
        const float svi = sv[i];
        const int* arow = adj + gi * N_NODES;

        float mx = -INFINITY;
        #pragma unroll
        for (int m = 0; m < 16; m++) {
            const int j = tj + 32 * m;
            float v = vals[ii][m] + su[j] + svi;
            v = arow[j] ? v : -INFINITY;
            vals[ii][m] = v;
            mx = fmaxf(mx, v);
        }
        #pragma unroll
        for (int o = 16; o; o >>= 1) mx = fmaxf(mx, __shfl_xor_sync(0xffffffffu, mx, o));

        float s = 0.f;
        #pragma unroll
        for (int m = 0; m < 16; m++) {
            const float e = __expf(vals[ii][m] - mx);
            vals[ii][m] = e;
            s += e;
        }
        #pragma unroll
        for (int o = 16; o; o >>= 1) s += __shfl_xor_sync(0xffffffffu, s, o);
        const float inv = 1.f / s;

        float* dst = d_attn + h * (N_NODES * N_NODES) + gi * N_NODES;
        #pragma unroll
        for (int m = 0; m < 16; m++)
            dst[tj + 32 * m] = vals[ii][m] * inv;
    }
}

// ---------------------------------------------------------------------------
// K3: out[i, h*64+f] = sum_j attn[h][i][j] * g_tgt[h][j][f]  (FFMA2, f-pairs)
// ---------------------------------------------------------------------------
__global__ __launch_bounds__(256) void k3_out(float* __restrict__ out) {
    __shared__ float sa[32][33];
    __shared__ float sb[32][64];

    const int i0 = blockIdx.x * 32;
    const int h  = blockIdx.y;
    const int t  = threadIdx.x;
    const int tf = t & 15, ti = t >> 4;

    const float* attn_h = d_attn + h * (N_NODES * N_NODES);
    const float* gt_h   = d_gtgt + h * (N_NODES * N_HID);

    u64 acc[2][2] = {};   // [ii][fp], f = 2tf + 32*fp (+1)

    for (int j0 = 0; j0 < N_NODES; j0 += 32) {
        #pragma unroll
        for (int k = 0; k < 4; k++) {
            const int lin = t + k * 256;
            const int i = lin >> 5, j = lin & 31;
            sa[i][j] = attn_h[(i0 + i) * N_NODES + j0 + j];
        }
        #pragma unroll
        for (int k = 0; k < 8; k++) {
            const int lin = t + k * 256;
            const int j = lin >> 6, f = lin & 63;
            sb[j][f] = gt_h[(j0 + j) * N_HID + f];
        }
        __syncthreads();
        #pragma unroll
        for (int j = 0; j < 32; j++) {
            const u64 b0 = *(const u64*)&sb[j][2 * tf];
            const u64 b1 = *(const u64*)&sb[j][2 * tf + 32];
            const float a0v = sa[2 * ti][j];
            const float a1v = sa[2 * ti + 1][j];
            const u64 a0 = pack2(a0v, a0v);
            const u64 a1 = pack2(a1v, a1v);
            acc[0][0] = fma2(a0, b0, acc[0][0]);
            acc[0][1] = fma2(a0, b1, acc[0][1]);
            acc[1][0] = fma2(a1, b0, acc[1][0]);
            acc[1][1] = fma2(a1, b1, acc[1][1]);
        }
        __syncthreads();
    }

    #pragma unroll
    for (int ii = 0; ii < 2; ii++) {
        const int i = i0 + 2 * ti + ii;
        float lo, hi;
        unpack2(acc[ii][0], lo, hi);
        *(float2*)&out[i * 512 + h * N_HID + 2 * tf]      = make_float2(lo, hi);
        unpack2(acc[ii][1], lo, hi);
        *(float2*)&out[i * 512 + h * N_HID + 2 * tf + 32] = make_float2(lo, hi);
    }
}

// ---------------------------------------------------------------------------
// K4: transpose d_attn[h][i][j] -> attention [i][j][h], float4 both sides.
// ---------------------------------------------------------------------------
__global__ __launch_bounds__(256) void k4_transpose(float* __restrict__ att_out) {
    __shared__ float s[8 * 516];
    const int i = blockIdx.x;
    const int t = threadIdx.x;

    #pragma unroll
    for (int k = 0; k < 4; k++) {
        const int lin = t + k * 256;               // 0..1023 float4 slots
        const int hh = lin >> 7, j4 = lin & 127;
        const float4 v = *(const float4*)&d_attn[hh * (N_NODES * N_NODES) + i * N_NODES + 4 * j4];
        *(float4*)&s[hh * 516 + 4 * j4] = v;
    }
    __syncthreads();

    float* dst = att_out + i * (N_NODES * N_HEADS);
    #pragma unroll
    for (int k = 0; k < 4; k++) {
        const int lin = t + k * 256;               // 0..1023 float4 slots
        const int j = lin >> 1, h0 = (lin & 1) * 4;
        const float4 v = make_float4(s[(h0 + 0) * 516 + j], s[(h0 + 1) * 516 + j],
                                     s[(h0 + 2) * 516 + j], s[(h0 + 3) * 516 + j]);
        *(float4*)&dst[4 * lin] = v;               // 4*lin = 8j + h0
    }
}

// ---------------------------------------------------------------------------
extern "C" void kernel_launch(void* const* d_in, const int* in_sizes, int n_in,
                              void* d_out, int out_size) {
    const float* x   = (const float*)d_in[0];  // h [1,512,512]
    const float* Ws  = (const float*)d_in[1];  // W_source [512,512]
    const float* Wt  = (const float*)d_in[2];  // W_target [512,512]
    const float* aw  = (const float*)d_in[3];  // attn_w [64]
    const int*   adj = (const int*)d_in[4];    // adjacency [512,512,1]

    float* out = (float*)d_out;
    float* att_out = out + N_NODES * N_HEADS * N_HID;

    cudaFuncSetAttribute(k2_scores, cudaFuncAttributeMaxDynamicSharedMemorySize,
                         K2_SMEM_BYTES);

    k1_gemm<<<dim3(8, 16), 256>>>(x, Ws, Wt, aw);
    k2_scores<<<dim3(16, 8), 256, K2_SMEM_BYTES>>>(aw, adj);
    k3_out<<<dim3(16, 8), 256>>>(out);
    if (out_size >= N_NODES * N_HEADS * N_HID + N_NODES * N_NODES * N_HEADS) {
        k4_transpose<<<N_NODES, 256>>>(att_out);
    }
}

// round 5
// speedup vs baseline: 1.6900x; 1.1039x over previous
#include <cuda_runtime.h>
#include <math.h>

#define N_NODES   512
#define IN_FEAT   512
#define N_HEADS   8
#define N_HID     64

typedef unsigned long long u64;

// Scratch (device globals: allocation-free rule)
__device__ float d_gsrc[N_HEADS * N_NODES * N_HID];   // [h][n][f]
__device__ float d_gtgt[N_HEADS * N_NODES * N_HID];   // [h][n][f]
__device__ float d_attn[N_HEADS * N_NODES * N_NODES]; // [h][i][j]
__device__ float d_u[N_HEADS * N_NODES];              // 0.6 * <w, gsrc[j]>
__device__ float d_v[N_HEADS * N_NODES];              // 0.6 * <w, gtgt[i]>

// ---- packed f32x2 helpers ----
__device__ __forceinline__ u64 pack2(float x, float y) {
    u64 r; asm("mov.b64 %0, {%1,%2};" : "=l"(r) : "f"(x), "f"(y)); return r;
}
__device__ __forceinline__ void unpack2(u64 v, float& x, float& y) {
    asm("mov.b64 {%0,%1}, %2;" : "=f"(x), "=f"(y) : "l"(v));
}
__device__ __forceinline__ u64 add2(u64 a, u64 b) {
    u64 d; asm("add.rn.f32x2 %0, %1, %2;" : "=l"(d) : "l"(a), "l"(b)); return d;
}
__device__ __forceinline__ u64 fma2(u64 a, u64 b, u64 c) {
    u64 d; asm("fma.rn.f32x2 %0, %1, %2, %3;" : "=l"(d) : "l"(a), "l"(b), "l"(c)); return d;
}

// ---------------------------------------------------------------------------
// K1: g = x @ W^T for both weights. 64n x 64r tile, 4x4 contiguous micro-tile,
// LDS.128 for both operands. Epilogue: g rows + u/v = 0.6*<attn_w, row>.
// ---------------------------------------------------------------------------
__global__ __launch_bounds__(256) void k1_gemm(const float* __restrict__ x,
                                               const float* __restrict__ Ws,
                                               const float* __restrict__ Wt,
                                               const float* __restrict__ aw) {
    __shared__ float At[16][68];   // [d][n] transposed
    __shared__ float Bt[16][68];   // [d][j] transposed

    const int n0 = blockIdx.x * 64;
    const int r0 = blockIdx.y * 64;           // 0..1023
    const float* W    = (r0 < 512) ? Ws : Wt;
    float*       gout = (r0 < 512) ? d_gsrc : d_gtgt;
    float*       uv   = (r0 < 512) ? d_u : d_v;
    const int rb = r0 & 511;
    const int h  = rb >> 6;

    const int t  = threadIdx.x;
    const int tx = t & 15, ty = t >> 4;       // rows 4ty+ii, cols 4tx+q

    u64 acc[4][2] = {};   // [ii][pair]: cols 4tx+2p .. 4tx+2p+1

    for (int k0 = 0; k0 < IN_FEAT; k0 += 16) {
        #pragma unroll
        for (int kk = 0; kk < 4; kk++) {
            const int lin = t + kk * 256;
            const int d = lin & 15, n = lin >> 4;
            At[d][n] = x[(n0 + n) * IN_FEAT + k0 + d];
            Bt[d][n] = W[(rb + n) * IN_FEAT + k0 + d];
        }
        __syncthreads();
        #pragma unroll
        for (int d2 = 0; d2 < 16; d2++) {
            const float4 a4 = *(const float4*)&At[d2][4 * ty];
            const u64*   bp = (const u64*)&Bt[d2][4 * tx];
            const u64 b0 = bp[0], b1 = bp[1];
            const float av[4] = {a4.x, a4.y, a4.z, a4.w};
            #pragma unroll
            for (int ii = 0; ii < 4; ii++) {
                const u64 a2 = pack2(av[ii], av[ii]);
                acc[ii][0] = fma2(a2, b0, acc[ii][0]);
                acc[ii][1] = fma2(a2, b1, acc[ii][1]);
            }
        }
        __syncthreads();
    }

    const float w0 = 0.6f * aw[4 * tx],     w1 = 0.6f * aw[4 * tx + 1];
    const float w2 = 0.6f * aw[4 * tx + 2], w3 = 0.6f * aw[4 * tx + 3];

    #pragma unroll
    for (int ii = 0; ii < 4; ii++) {
        const int n = n0 + 4 * ty + ii;
        float* dst = gout + h * (N_NODES * N_HID) + n * N_HID;
        float c0, c1, c2, c3;
        unpack2(acc[ii][0], c0, c1);
        unpack2(acc[ii][1], c2, c3);
        *(float4*)&dst[4 * tx] = make_float4(c0, c1, c2, c3);
        float p = w0 * c0 + w1 * c1 + w2 * c2 + w3 * c3;
        #pragma unroll
        for (int off = 8; off; off >>= 1)
            p += __shfl_down_sync(0xffffffffu, p, off, 16);
        if (tx == 0) uv[h * N_NODES + n] = p;
    }
}

// ---------------------------------------------------------------------------
// K2: A[i,j] = sum_f (0.4 w_f)|gs_jf + gt_if| (f32x2 + LOP3 abs), then
// score = A + u_j + v_i, adjacency mask, softmax over j -> d_attn[h][i][j].
// 512 threads (16 warps, warp owns 2 rows); scores stay in registers.
// ---------------------------------------------------------------------------
#define K2_SMEM_BYTES (32 * 512 * 8 + (32 * 66 + 64 + 512 + 32) * 4)

__global__ __launch_bounds__(512, 1) void k2_scores(const float* __restrict__ aw,
                                                    const int*   __restrict__ adj) {
    extern __shared__ char k2sm[];
    u64*   sgs = (u64*)k2sm;                       // [32 fp][512 j]
    float* sgt = (float*)(k2sm + 32 * 512 * 8);    // [32 i][66]
    float* sw  = sgt + 32 * 66;                    // 64 (0.4*w)
    float* su  = sw + 64;                          // 512
    float* sv  = su + 512;                         // 32

    const int h  = blockIdx.y;
    const int i0 = blockIdx.x * 32;
    const int t  = threadIdx.x;

    const float* gs_h = d_gsrc + h * (N_NODES * N_HID);
    const float* gt_h = d_gtgt + h * (N_NODES * N_HID);

    if (t < 64) sw[t] = 0.4f * aw[t];
    su[t] = d_u[h * N_NODES + t];
    if (t < 32) sv[t] = d_v[h * N_NODES + i0 + t];

    #pragma unroll
    for (int k = 0; k < 4; k++) {
        const int lin = t + k * 512;
        const int i = lin >> 6, f = lin & 63;
        sgt[i * 66 + f] = gt_h[(i0 + i) * N_HID + f];
    }
    #pragma unroll
    for (int k = 0; k < 16; k++) {
        const int lin = t + k * 512;           // over 8192 float4
        const int j = lin & 511, f4 = lin >> 9;
        const float4 vv = *(const float4*)&gs_h[j * N_HID + 4 * f4];
        sgs[(2 * f4)     * 512 + j] = pack2(vv.x, vv.y);
        sgs[(2 * f4 + 1) * 512 + j] = pack2(vv.z, vv.w);
    }
    __syncthreads();

    const int wid = t >> 5, tj = t & 31;       // warp wid owns rows 2wid, 2wid+1
    const u64 ABS2 = 0x7FFFFFFF7FFFFFFFULL;
    float vals[2][16];

    #pragma unroll
    for (int jt = 0; jt < 4; jt++) {
        u64 acc[2][4] = {};
        #pragma unroll 8
        for (int fp = 0; fp < 32; fp++) {
            const u64 w2 = *(const u64*)&sw[2 * fp];
            const u64 g0 = *(const u64*)&sgt[(2 * wid)     * 66 + 2 * fp];
            const u64 g1 = *(const u64*)&sgt[(2 * wid + 1) * 66 + 2 * fp];
            #pragma unroll
            for (int jj = 0; jj < 4; jj++) {
                const u64 s2 = sgs[fp * 512 + tj + 32 * (4 * jt + jj)];
                const u64 t0 = add2(g0, s2) & ABS2;
                const u64 t1 = add2(g1, s2) & ABS2;
                acc[0][jj] = fma2(t0, w2, acc[0][jj]);
                acc[1][jj] = fma2(t1, w2, acc[1][jj]);
            }
        }
        #pragma unroll
        for (int ii = 0; ii < 2; ii++)
            #pragma unroll
            for (int jj = 0; jj < 4; jj++) {
                float lo, hi; unpack2(acc[ii][jj], lo, hi);
                vals[ii][4 * jt + jj] = lo + hi;
            }
    }

    // Softmax per row (register-resident; lane tj holds j = tj + 32m)
    #pragma unroll
    for (int ii = 0; ii < 2; ii++) {
        const int i  = 2 * wid + ii;
        const int gi = i0 + i;
        const float svi = sv[i];
        const int* arow = adj + gi * N_NODES;

        float mx = -INFINITY;
        #pragma unroll
        for (int m = 0; m < 16; m++) {
            const int j = tj + 32 * m;
            float v = vals[ii][m] + su[j] + svi;
            v = arow[j] ? v : -INFINITY;
            vals[ii][m] = v;
            mx = fmaxf(mx, v);
        }
        #pragma unroll
        for (int o = 16; o; o >>= 1) mx = fmaxf(mx, __shfl_xor_sync(0xffffffffu, mx, o));

        float s = 0.f;
        #pragma unroll
        for (int m = 0; m < 16; m++) {
            const float e = __expf(vals[ii][m] - mx);
            vals[ii][m] = e;
            s += e;
        }
        #pragma unroll
        for (int o = 16; o; o >>= 1) s += __shfl_xor_sync(0xffffffffu, s, o);
        const float inv = 1.f / s;

        float* dst = d_attn + h * (N_NODES * N_NODES) + gi * N_NODES;
        #pragma unroll
        for (int m = 0; m < 16; m++)
            dst[tj + 32 * m] = vals[ii][m] * inv;
    }
}

// ---------------------------------------------------------------------------
// K3: out[i, h*64+f] = sum_j attn[h][i][j] * g_tgt[h][j][f]
// 2i x 4f (contiguous quad) micro-tile, LDS.128 b-loads.
// ---------------------------------------------------------------------------
__global__ __launch_bounds__(256) void k3_out(float* __restrict__ out) {
    __shared__ float sa[32][33];
    __shared__ float sb[32][68];

    const int i0 = blockIdx.x * 32;
    const int h  = blockIdx.y;
    const int t  = threadIdx.x;
    const int tf = t & 15, ti = t >> 4;        // f quad 4tf, rows 2ti, 2ti+1

    const float* attn_h = d_attn + h * (N_NODES * N_NODES);
    const float* gt_h   = d_gtgt + h * (N_NODES * N_HID);

    u64 acc[2][2] = {};   // [ii][pair]

    for (int j0 = 0; j0 < N_NODES; j0 += 32) {
        #pragma unroll
        for (int k = 0; k < 4; k++) {
            const int lin = t + k * 256;
            const int i = lin >> 5, j = lin & 31;
            sa[i][j] = attn_h[(i0 + i) * N_NODES + j0 + j];
        }
        #pragma unroll
        for (int k = 0; k < 8; k++) {
            const int lin = t + k * 256;
            const int j = lin >> 6, f = lin & 63;
            sb[j][f] = gt_h[(j0 + j) * N_HID + f];
        }
        __syncthreads();
        #pragma unroll
        for (int j = 0; j < 32; j++) {
            const u64* bp = (const u64*)&sb[j][4 * tf];
            const u64 b0 = bp[0], b1 = bp[1];
            const float a0v = sa[2 * ti][j];
            const float a1v = sa[2 * ti + 1][j];
            const u64 a0 = pack2(a0v, a0v);
            const u64 a1 = pack2(a1v, a1v);
            acc[0][0] = fma2(a0, b0, acc[0][0]);
            acc[0][1] = fma2(a0, b1, acc[0][1]);
            acc[1][0] = fma2(a1, b0, acc[1][0]);
            acc[1][1] = fma2(a1, b1, acc[1][1]);
        }
        __syncthreads();
    }

    #pragma unroll
    for (int ii = 0; ii < 2; ii++) {
        const int i = i0 + 2 * ti + ii;
        float c0, c1, c2, c3;
        unpack2(acc[ii][0], c0, c1);
        unpack2(acc[ii][1], c2, c3);
        *(float4*)&out[i * 512 + h * N_HID + 4 * tf] = make_float4(c0, c1, c2, c3);
    }
}

// ---------------------------------------------------------------------------
// K4: d_attn[h][i][j] -> attention [i][j][h]. No smem: gather 2 scalars per
// (j, h-pair), store coalesced float2. Grid 128 x 4 rows, 64 loads in flight.
// ---------------------------------------------------------------------------
__global__ __launch_bounds__(256) void k4_transpose(float* __restrict__ att_out) {
    const int t  = threadIdx.x;
    const int i0 = blockIdx.x * 4;

    #pragma unroll
    for (int ii = 0; ii < 4; ii++) {
        const int i = i0 + ii;
        #pragma unroll
        for (int k = 0; k < 8; k++) {
            const int u  = t + k * 256;        // 0..2047
            const int j  = u >> 2, hp = u & 3;
            const float a = d_attn[(2 * hp)     * (N_NODES * N_NODES) + i * N_NODES + j];
            const float b = d_attn[(2 * hp + 1) * (N_NODES * N_NODES) + i * N_NODES + j];
            *(float2*)&att_out[i * (N_NODES * N_HEADS) + j * N_HEADS + 2 * hp] =
                make_float2(a, b);
        }
    }
}

// ---------------------------------------------------------------------------
extern "C" void kernel_launch(void* const* d_in, const int* in_sizes, int n_in,
                              void* d_out, int out_size) {
    const float* x   = (const float*)d_in[0];  // h [1,512,512]
    const float* Ws  = (const float*)d_in[1];  // W_source [512,512]
    const float* Wt  = (const float*)d_in[2];  // W_target [512,512]
    const float* aw  = (const float*)d_in[3];  // attn_w [64]
    const int*   adj = (const int*)d_in[4];    // adjacency [512,512,1]

    float* out = (float*)d_out;
    float* att_out = out + N_NODES * N_HEADS * N_HID;

    cudaFuncSetAttribute(k2_scores, cudaFuncAttributeMaxDynamicSharedMemorySize,
                         K2_SMEM_BYTES);

    k1_gemm<<<dim3(8, 16), 256>>>(x, Ws, Wt, aw);
    k2_scores<<<dim3(16, 8), 512, K2_SMEM_BYTES>>>(aw, adj);
    k3_out<<<dim3(16, 8), 256>>>(out);
    if (out_size >= N_NODES * N_HEADS * N_HID + N_NODES * N_NODES * N_HEADS) {
        k4_transpose<<<128, 256>>>(att_out);
    }
}